// round 11
// baseline (speedup 1.0000x reference)
#include <cuda_runtime.h>

// Problem constants (fixed by setup_inputs)
#define T_LEN 8192
#define H_HEADS 16
#define B_BATCH 2
#define P_DIM 64
#define N_DIM 64
#define BH (B_BATCH * H_HEADS)   // 32

#define KS 32                    // timesteps per slice = per work item
#define NSLICE (T_LEN / KS)      // 256
#define PHALF 32                 // p-split: block owns 32 of 64 p-rows
#define GPS 8                    // state blocks per (bh, p-half), grid-stride
// exp(-14) ~ 8e-7: dropped tail perturbs result ~4e-6 relative; gate is 1e-3.
#define THRESH 14.0f

// ---- packed fp32x2 helpers (sm_100+; PTX-only) ----
__device__ __forceinline__ unsigned long long fma2(unsigned long long a,
                                                   unsigned long long b,
                                                   unsigned long long c) {
    unsigned long long d;
    asm("fma.rn.f32x2 %0, %1, %2, %3;" : "=l"(d) : "l"(a), "l"(b), "l"(c));
    return d;
}
__device__ __forceinline__ unsigned long long pack2(float x) {
    unsigned long long d;
    asm("mov.b64 %0, {%1, %1};" : "=l"(d) : "f"(x));
    return d;
}

// ---------------------------------------------------------------------------
// Fused state kernel: grid (GPS, BH, 2); block (j0, bh, z) handles items
// j = j0, j0+GPS, ... (newest slice first) for a 32x64 output half-tile.
// Each block computes its own tail = sum(A beyond slice) — j*32 elements —
// overlapped with the X/B tile loads. Dead blocks (tail < -THRESH) break;
// tails are monotone in j (a <= 0), so all later items are dead too.
// ---------------------------------------------------------------------------
__global__ void __launch_bounds__(128)
state_kernel(const float* __restrict__ X, const float* __restrict__ Bm,
             const float* __restrict__ A, float* __restrict__ out) {
    int bh = blockIdx.y;
    int ph = blockIdx.z * PHALF;
    int tid = threadIdx.x;
    int lane = tid & 31, wid = tid >> 5;
    int b = bh / H_HEADS, hh = bh % H_HEADS;

    __shared__ float s_red[4];
    __shared__ float s_wt[KS];
    __shared__ float sX[KS][PHALF];
    __shared__ float sB[KS][N_DIM];

    const float* Ab = A + (size_t)b * T_LEN * H_HEADS + hh;

    // loader mappings
    int lrowB = tid >> 4, lcolB = (tid & 15) << 2;   // B: 8 rows x 16 f4, x4
    int lrowX = tid >> 3, lcolX = (tid & 7) << 2;    // X: 16 rows x 8 f4, x2
    // compute tile
    int p0 = (tid >> 4) << 2;   // 0..28
    int n0 = (tid & 15) << 2;   // 0..60
    unsigned long long acc[4][2] = {};
    bool any = false;

    for (int j = blockIdx.x; j < NSLICE; j += GPS) {
        int slice = NSLICE - 1 - j;
        int t0 = slice * KS;

        // --- issue X/B tile loads FIRST (the long pole) ---
        float4 xr[2], br[4];
#pragma unroll
        for (int k = 0; k < 2; k++) {
            int r = k * 16 + lrowX;
            xr[k] = *(const float4*)(X + (((size_t)b * T_LEN + t0 + r) * H_HEADS + hh) * P_DIM
                                       + ph + lcolX);
        }
#pragma unroll
        for (int k = 0; k < 4; k++) {
            int r = k * 8 + lrowB;
            br[k] = *(const float4*)(Bm + (((size_t)b * T_LEN + t0 + r) * H_HEADS + hh) * P_DIM
                                        + lcolB);
        }

        // --- this slice's a values (warp 0) ---
        float a = 0.f;
        if (tid < KS) a = Ab[(size_t)(t0 + tid) * H_HEADS];

        // --- tail = sum of A beyond slice end: j*32 elements, all threads ---
        int elems = j * KS;
        int t1 = t0 + KS;
        float part = 0.f;
        for (int i = tid; i < elems; i += 128)
            part += Ab[(size_t)(t1 + i) * H_HEADS];
#pragma unroll
        for (int off = 16; off > 0; off >>= 1)
            part += __shfl_xor_sync(0xffffffffu, part, off);
        if (any) __syncthreads();        // prev item's s_red/s_wt readers done
        if (lane == 0) s_red[wid] = part;
        __syncthreads();                 // s_red ready
        float tail = s_red[0] + s_red[1] + s_red[2] + s_red[3];

        if (tail < -THRESH) break;       // dead: this and all later items

        // weights: warp 0, inclusive suffix scan of a within slice
        if (tid < KS) {
            float s = a;
#pragma unroll
            for (int off = 1; off < 32; off <<= 1) {
                float tmp = __shfl_down_sync(0xffffffffu, s, off);
                if (lane + off < 32) s += tmp;
            }
            s_wt[tid] = expf(tail + s - a);   // exclusive suffix + tail
        }
        __syncthreads();                 // s_wt visible

        // stage (X scaled by weight)
#pragma unroll
        for (int k = 0; k < 2; k++) {
            int r = k * 16 + lrowX;
            float w = s_wt[r];
            float4 xv = xr[k];
            xv.x *= w; xv.y *= w; xv.z *= w; xv.w *= w;
            *(float4*)&sX[r][lcolX] = xv;
        }
#pragma unroll
        for (int k = 0; k < 4; k++)
            *(float4*)&sB[k * 8 + lrowB][lcolB] = br[k];
        __syncthreads();                 // staging visible

#pragma unroll
        for (int tt = 0; tt < KS; tt++) {
            float4 xv = *(const float4*)&sX[tt][p0];
            ulonglong2 bp = *(const ulonglong2*)&sB[tt][n0];
            unsigned long long bv[2] = {bp.x, bp.y};
            float xs[4] = {xv.x, xv.y, xv.z, xv.w};
#pragma unroll
            for (int i = 0; i < 4; i++) {
                unsigned long long x2 = pack2(xs[i]);
#pragma unroll
                for (int jj = 0; jj < 2; jj++)
                    acc[i][jj] = fma2(x2, bv[jj], acc[i][jj]);
            }
        }
        any = true;
    }

    if (!any) return;

    // single epilogue: one red.v4 per owned output row
    float* ob = out + (size_t)bh * (P_DIM * N_DIM);
#pragma unroll
    for (int i = 0; i < 4; i++) {
        float v[4];
#pragma unroll
        for (int jj = 0; jj < 2; jj++)
            asm("mov.b64 {%0, %1}, %2;" : "=f"(v[2 * jj]), "=f"(v[2 * jj + 1])
                                        : "l"(acc[i][jj]));
        float* p = &ob[(ph + p0 + i) * N_DIM + n0];
        asm volatile("red.global.add.v4.f32 [%0], {%1, %2, %3, %4};"
                     :: "l"(p), "f"(v[0]), "f"(v[1]), "f"(v[2]), "f"(v[3]) : "memory");
    }
}

// ---------------------------------------------------------------------------
extern "C" void kernel_launch(void* const* d_in, const int* in_sizes, int n_in,
                              void* d_out, int out_size) {
    const float* X = (const float*)d_in[0];
    const float* A = (const float*)d_in[1];
    const float* B = (const float*)d_in[2];
    float* out = (float*)d_out;

    cudaMemsetAsync(d_out, 0, (size_t)out_size * sizeof(float));
    dim3 gS(GPS, BH, 2);
    state_kernel<<<gS, 128>>>(X, B, A, out);
}